// round 4
// baseline (speedup 1.0000x reference)
#include <cuda_runtime.h>
#include <cuda_bf16.h>

#define CC      2048
#define HW      49
#define SIDE    7
#define CGROUPS 8
#define NTHR    512
#define SPLIT   8
#define CPS     (CC / SPLIT)    // 256 channels per CTA
#define NMAX    256

// scratch: [n][split][p][5]
__device__ float g_scratch[NMAX * SPLIT * HW * 5];
__device__ int   g_count[NMAX];   // zero-init; last block resets its slot

__global__ __launch_bounds__(NTHR, 3)
void rpcp_fused_kernel(const float* __restrict__ x,
                       const float* __restrict__ Wlin,
                       const float* __restrict__ bias,
                       float* __restrict__ out,
                       float* __restrict__ scratch)
{
    __shared__ float4 wsh[CPS];
    __shared__ float  acc[CGROUPS][HW][5];
    __shared__ int    s_last;
    // epilogue scratch
    __shared__ float  fin[HW][5];
    __shared__ float  gaps[HW];
    __shared__ float  dls[HW];
    __shared__ int    s_idx;
    __shared__ float  s_gmean;

    const int tid = threadIdx.x;
    const int n   = blockIdx.x >> 3;            // SPLIT = 8
    const int sp  = blockIdx.x & (SPLIT - 1);
    const int c0  = sp * CPS;

    // pack weight slice: {W1_0, W1_1, W2_0, W2_1} per channel
    for (int c = tid; c < CPS; c += NTHR) {
        const int cc = c0 + c;
        wsh[c] = make_float4(Wlin[cc],
                             Wlin[2 * CC + cc],
                             Wlin[CC + cc],
                             Wlin[3 * CC + cc]);
    }
    __syncthreads();

    const int p  = tid & 63;     // 0..48 active
    const int cg = tid >> 6;     // 0..7

    if (p < HW) {
        float s = 0.f, a0 = 0.f, a1 = 0.f, d0 = 0.f, d1 = 0.f;
        const float* xp = x + (size_t)n * CC * HW + (size_t)c0 * HW + p;
        #pragma unroll 8
        for (int c = cg; c < CPS; c += CGROUPS) {   // exactly 32 iterations
            float  v = __ldg(xp + c * HW);          // coalesced across lanes
            float4 w = wsh[c];
            s  += v;
            a0 = fmaf(v, w.x, a0);
            a1 = fmaf(v, w.y, a1);
            d0 = fmaf(v, w.z, d0);
            d1 = fmaf(v, w.w, d1);
        }
        acc[cg][p][0] = s;  acc[cg][p][1] = a0; acc[cg][p][2] = a1;
        acc[cg][p][3] = d0; acc[cg][p][4] = d1;
    }
    __syncthreads();

    if (tid < HW * 5) {
        const int pp = tid / 5, k = tid % 5;
        float t = 0.f;
        #pragma unroll
        for (int g = 0; g < CGROUPS; g++) t += acc[g][pp][k];
        scratch[((n * SPLIT + sp) * HW + pp) * 5 + k] = t;
    }

    // last-CTA-done handoff
    __threadfence();
    __syncthreads();
    if (tid == 0) {
        int old = atomicAdd(&g_count[n], 1);
        s_last = (old == SPLIT - 1);
    }
    __syncthreads();
    if (!s_last) return;
    __threadfence();   // acquire side: see all 8 CTAs' scratch

    // ---- epilogue: this CTA finishes image n ----
    if (tid < HW * 5) {
        const int pp = tid / 5, k = tid % 5;
        float t = 0.f;
        #pragma unroll
        for (int g = 0; g < SPLIT; g++)
            t += scratch[((n * SPLIT + g) * HW + pp) * 5 + k];
        fin[pp][k] = t;
    }
    __syncthreads();

    // warp-shuffle argmax over channel-sum (first max wins ties)
    if (tid < 32) {
        float v  = fin[tid][0];
        int   bi = tid;
        if (tid + 32 < HW) {
            float v2 = fin[tid + 32][0];
            if (v2 > v) { v = v2; bi = tid + 32; }
        }
        #pragma unroll
        for (int off = 16; off > 0; off >>= 1) {
            float ov = __shfl_down_sync(0xffffffffu, v,  off);
            int   oi = __shfl_down_sync(0xffffffffu, bi, off);
            if (ov > v || (ov == v && oi < bi)) { v = ov; bi = oi; }
        }
        if (tid == 0) { s_idx = bi; g_count[n] = 0; }   // reset counter for replay
    }
    __syncthreads();
    const int idx = s_idx;

    if (tid < HW) {
        const float A0 = fin[idx][1];
        const float A1 = fin[idx][2];
        float pr0 = fin[tid][3] + A0 + bias[0];
        float pr1 = fin[tid][4] + A1 + bias[1];
        pr0 = fmaxf(pr0, 0.f);
        pr1 = fmaxf(pr1, 0.f);
        if (tid == idx) { pr0 = 0.f; pr1 = 0.f; }

        const float ri = (float)(tid / SIDE - idx / SIDE) * (1.f / (float)SIDE);
        const float rj = (float)(tid % SIDE - idx % SIDE) * (1.f / (float)SIDE);
        const float rd = sqrtf(ri * ri + rj * rj);
        const float ang = (atan2f(rj, ri) * (1.f / 3.14159265358979323846f) + 1.f) * 0.5f;

        float dl = pr0 - rd; dl *= dl;
        float g  = pr1 - ang;
        if (g < 0.f) g += 1.f;
        gaps[tid] = g;
        dls[tid]  = dl;
    }
    __syncthreads();

    // warp-shuffle mean of gaps
    if (tid < 32) {
        float t = (tid < HW) ? gaps[tid] : 0.f;
        if (tid + 32 < HW) t += gaps[tid + 32];
        #pragma unroll
        for (int off = 16; off > 0; off >>= 1)
            t += __shfl_down_sync(0xffffffffu, t, off);
        if (tid == 0) s_gmean = t * (1.f / (float)HW);
    }
    __syncthreads();

    if (tid < HW) {
        float g = gaps[tid] - s_gmean;
        out[n * HW + tid] = dls[tid] + g * g;
    }
}

extern "C" void kernel_launch(void* const* d_in, const int* in_sizes, int n_in,
                              void* d_out, int out_size)
{
    const float* x    = (const float*)d_in[0];
    const float* Wlin = (const float*)d_in[1];
    const float* b    = (const float*)d_in[2];
    float*       out  = (float*)d_out;

    const int N = in_sizes[0] / (CC * HW);   // 256

    float* scratch = nullptr;
    cudaGetSymbolAddress((void**)&scratch, g_scratch);

    rpcp_fused_kernel<<<N * SPLIT, NTHR>>>(x, Wlin, b, out, scratch);
}

// round 5
// speedup vs baseline: 1.0558x; 1.0558x over previous
#include <cuda_runtime.h>
#include <cuda_bf16.h>

#define CC      2048
#define HW      49
#define SIDE    7
#define CGROUPS 8
#define NTHR    512
#define SPLIT   8
#define CPS     (CC / SPLIT)    // 256 channels per CTA
#define NMAX    256

// scratch: [n][split][p][5]
__device__ float g_scratch[NMAX * SPLIT * HW * 5];
__device__ int   g_count[NMAX];   // zero-init; last block resets its slot

__global__ __launch_bounds__(NTHR, 3)
void rpcp_fused_kernel(const float* __restrict__ x,
                       const float* __restrict__ Wlin,
                       const float* __restrict__ bias,
                       float* __restrict__ out,
                       float* __restrict__ scratch)
{
    __shared__ float4 wsh[CPS];
    __shared__ float  acc[CGROUPS][HW][5];
    __shared__ int    s_last;
    // epilogue scratch
    __shared__ float  fin[HW][5];
    __shared__ float  gaps[HW];
    __shared__ float  dls[HW];
    __shared__ int    s_idx;
    __shared__ float  s_gmean;

    const int tid = threadIdx.x;
    const int n   = blockIdx.x >> 3;            // SPLIT = 8
    const int sp  = blockIdx.x & (SPLIT - 1);
    const int c0  = sp * CPS;

    // pack weight slice: {W1_0, W1_1, W2_0, W2_1} per channel
    for (int c = tid; c < CPS; c += NTHR) {
        const int cc = c0 + c;
        wsh[c] = make_float4(Wlin[cc],
                             Wlin[2 * CC + cc],
                             Wlin[CC + cc],
                             Wlin[3 * CC + cc]);
    }
    __syncthreads();

    const int p  = tid & 63;     // 0..48 active
    const int cg = tid >> 6;     // 0..7

    if (p < HW) {
        float s = 0.f, a0 = 0.f, a1 = 0.f, d0 = 0.f, d1 = 0.f;
        const float* xp = x + (size_t)n * CC * HW + (size_t)c0 * HW + p;
        #pragma unroll 8
        for (int c = cg; c < CPS; c += CGROUPS) {   // exactly 32 iterations
            float  v = __ldg(xp + c * HW);          // coalesced across lanes
            float4 w = wsh[c];
            s  += v;
            a0 = fmaf(v, w.x, a0);
            a1 = fmaf(v, w.y, a1);
            d0 = fmaf(v, w.z, d0);
            d1 = fmaf(v, w.w, d1);
        }
        acc[cg][p][0] = s;  acc[cg][p][1] = a0; acc[cg][p][2] = a1;
        acc[cg][p][3] = d0; acc[cg][p][4] = d1;
    }
    __syncthreads();

    if (tid < HW * 5) {
        const int pp = tid / 5, k = tid % 5;
        float t = 0.f;
        #pragma unroll
        for (int g = 0; g < CGROUPS; g++) t += acc[g][pp][k];
        scratch[((n * SPLIT + sp) * HW + pp) * 5 + k] = t;
    }

    // last-CTA-done handoff. Fences by ONE thread only — cumulative release/
    // acquire via bar.sync carries happens-before for all threads' stores
    // (same pattern as cooperative-groups grid.sync).
    __syncthreads();
    if (tid == 0) {
        __threadfence();                       // release (covers whole CTA via bar)
        int old = atomicAdd(&g_count[n], 1);
        s_last = (old == SPLIT - 1);
        if (s_last) __threadfence();           // acquire: see all 8 CTAs' scratch
    }
    __syncthreads();
    if (!s_last) return;

    // ---- epilogue: this CTA finishes image n ----
    if (tid < HW * 5) {
        const int pp = tid / 5, k = tid % 5;
        float t = 0.f;
        #pragma unroll
        for (int g = 0; g < SPLIT; g++)
            t += scratch[((n * SPLIT + g) * HW + pp) * 5 + k];
        fin[pp][k] = t;
    }
    __syncthreads();

    // warp-shuffle argmax over channel-sum (first max wins ties)
    if (tid < 32) {
        float v  = fin[tid][0];
        int   bi = tid;
        if (tid + 32 < HW) {
            float v2 = fin[tid + 32][0];
            if (v2 > v) { v = v2; bi = tid + 32; }
        }
        #pragma unroll
        for (int off = 16; off > 0; off >>= 1) {
            float ov = __shfl_down_sync(0xffffffffu, v,  off);
            int   oi = __shfl_down_sync(0xffffffffu, bi, off);
            if (ov > v || (ov == v && oi < bi)) { v = ov; bi = oi; }
        }
        if (tid == 0) { s_idx = bi; g_count[n] = 0; }   // reset counter for replay
    }
    __syncthreads();
    const int idx = s_idx;

    if (tid < HW) {
        const float A0 = fin[idx][1];
        const float A1 = fin[idx][2];
        float pr0 = fin[tid][3] + A0 + bias[0];
        float pr1 = fin[tid][4] + A1 + bias[1];
        pr0 = fmaxf(pr0, 0.f);
        pr1 = fmaxf(pr1, 0.f);
        if (tid == idx) { pr0 = 0.f; pr1 = 0.f; }

        const float ri = (float)(tid / SIDE - idx / SIDE) * (1.f / (float)SIDE);
        const float rj = (float)(tid % SIDE - idx % SIDE) * (1.f / (float)SIDE);
        const float rd = sqrtf(ri * ri + rj * rj);
        const float ang = (atan2f(rj, ri) * (1.f / 3.14159265358979323846f) + 1.f) * 0.5f;

        float dl = pr0 - rd; dl *= dl;
        float g  = pr1 - ang;
        if (g < 0.f) g += 1.f;
        gaps[tid] = g;
        dls[tid]  = dl;
    }
    __syncthreads();

    // warp-shuffle mean of gaps
    if (tid < 32) {
        float t = (tid < HW) ? gaps[tid] : 0.f;
        if (tid + 32 < HW) t += gaps[tid + 32];
        #pragma unroll
        for (int off = 16; off > 0; off >>= 1)
            t += __shfl_down_sync(0xffffffffu, t, off);
        if (tid == 0) s_gmean = t * (1.f / (float)HW);
    }
    __syncthreads();

    if (tid < HW) {
        float g = gaps[tid] - s_gmean;
        out[n * HW + tid] = dls[tid] + g * g;
    }
}

extern "C" void kernel_launch(void* const* d_in, const int* in_sizes, int n_in,
                              void* d_out, int out_size)
{
    const float* x    = (const float*)d_in[0];
    const float* Wlin = (const float*)d_in[1];
    const float* b    = (const float*)d_in[2];
    float*       out  = (float*)d_out;

    const int N = in_sizes[0] / (CC * HW);   // 256

    float* scratch = nullptr;
    cudaGetSymbolAddress((void**)&scratch, g_scratch);

    rpcp_fused_kernel<<<N * SPLIT, NTHR>>>(x, Wlin, b, out, scratch);
}

// round 6
// speedup vs baseline: 1.1202x; 1.0611x over previous
#include <cuda_runtime.h>
#include <cuda_bf16.h>

#define CC      2048
#define HW      49
#define SIDE    7
#define CGROUPS 8
#define NTHR    512
#define SPLIT   8
#define CPS     (CC / SPLIT)    // 256 channels per CTA
#define NMAX    256

// scratch: [n][split][p][5]
__device__ float g_scratch[NMAX * SPLIT * HW * 5];
__device__ int   g_count[NMAX];   // zero-init; last block resets its slot

__global__ __launch_bounds__(NTHR, 2)   // occ-2: 64-reg budget -> high MLP
void rpcp_fused_kernel(const float* __restrict__ x,
                       const float* __restrict__ Wlin,
                       const float* __restrict__ bias,
                       float* __restrict__ out,
                       float* __restrict__ scratch)
{
    __shared__ float4 wsh[CPS];
    __shared__ float  acc[CGROUPS][HW][5];
    __shared__ int    s_last;
    // epilogue scratch
    __shared__ float  fin[HW][5];
    __shared__ float  gaps[HW];
    __shared__ float  dls[HW];
    __shared__ int    s_idx;
    __shared__ float  s_gmean;

    const int tid = threadIdx.x;
    const int n   = blockIdx.x >> 3;            // SPLIT = 8
    const int sp  = blockIdx.x & (SPLIT - 1);
    const int c0  = sp * CPS;

    // pack weight slice: {W1_0, W1_1, W2_0, W2_1} per channel
    for (int c = tid; c < CPS; c += NTHR) {
        const int cc = c0 + c;
        wsh[c] = make_float4(Wlin[cc],
                             Wlin[2 * CC + cc],
                             Wlin[CC + cc],
                             Wlin[3 * CC + cc]);
    }
    __syncthreads();

    const int p  = tid & 63;     // 0..48 active
    const int cg = tid >> 6;     // 0..7

    if (p < HW) {
        float s = 0.f, a0 = 0.f, a1 = 0.f, d0 = 0.f, d1 = 0.f;
        const float* xp = x + (size_t)n * CC * HW + (size_t)c0 * HW + p;

        // 4 blocks x 8 front-batched independent loads (MLP_p1 = 8)
        #pragma unroll
        for (int k = 0; k < 4; k++) {
            float v[8];
            #pragma unroll
            for (int u = 0; u < 8; u++) {
                const int c = cg + (k * 8 + u) * CGROUPS;
                v[u] = __ldg(xp + c * HW);
            }
            #pragma unroll
            for (int u = 0; u < 8; u++) {
                const int c = cg + (k * 8 + u) * CGROUPS;
                const float4 w = wsh[c];
                s  += v[u];
                a0 = fmaf(v[u], w.x, a0);
                a1 = fmaf(v[u], w.y, a1);
                d0 = fmaf(v[u], w.z, d0);
                d1 = fmaf(v[u], w.w, d1);
            }
        }
        acc[cg][p][0] = s;  acc[cg][p][1] = a0; acc[cg][p][2] = a1;
        acc[cg][p][3] = d0; acc[cg][p][4] = d1;
    }
    __syncthreads();

    if (tid < HW * 5) {
        const int pp = tid / 5, k = tid % 5;
        float t = 0.f;
        #pragma unroll
        for (int g = 0; g < CGROUPS; g++) t += acc[g][pp][k];
        scratch[((n * SPLIT + sp) * HW + pp) * 5 + k] = t;
    }

    // last-CTA-done handoff; fences by one thread only (cumulative via bar.sync)
    __syncthreads();
    if (tid == 0) {
        __threadfence();                       // release
        int old = atomicAdd(&g_count[n], 1);
        s_last = (old == SPLIT - 1);
        if (s_last) __threadfence();           // acquire
    }
    __syncthreads();
    if (!s_last) return;

    // ---- epilogue: this CTA finishes image n ----
    if (tid < HW * 5) {
        const int pp = tid / 5, k = tid % 5;
        float t = 0.f;
        #pragma unroll
        for (int g = 0; g < SPLIT; g++)
            t += scratch[((n * SPLIT + g) * HW + pp) * 5 + k];
        fin[pp][k] = t;
    }
    __syncthreads();

    // warp-shuffle argmax over channel-sum (first max wins ties)
    if (tid < 32) {
        float v  = fin[tid][0];
        int   bi = tid;
        if (tid + 32 < HW) {
            float v2 = fin[tid + 32][0];
            if (v2 > v) { v = v2; bi = tid + 32; }
        }
        #pragma unroll
        for (int off = 16; off > 0; off >>= 1) {
            float ov = __shfl_down_sync(0xffffffffu, v,  off);
            int   oi = __shfl_down_sync(0xffffffffu, bi, off);
            if (ov > v || (ov == v && oi < bi)) { v = ov; bi = oi; }
        }
        if (tid == 0) { s_idx = bi; g_count[n] = 0; }   // reset for replay
    }
    __syncthreads();
    const int idx = s_idx;

    if (tid < HW) {
        const float A0 = fin[idx][1];
        const float A1 = fin[idx][2];
        float pr0 = fin[tid][3] + A0 + bias[0];
        float pr1 = fin[tid][4] + A1 + bias[1];
        pr0 = fmaxf(pr0, 0.f);
        pr1 = fmaxf(pr1, 0.f);
        if (tid == idx) { pr0 = 0.f; pr1 = 0.f; }

        const float ri = (float)(tid / SIDE - idx / SIDE) * (1.f / (float)SIDE);
        const float rj = (float)(tid % SIDE - idx % SIDE) * (1.f / (float)SIDE);
        const float rd = sqrtf(ri * ri + rj * rj);
        const float ang = (atan2f(rj, ri) * (1.f / 3.14159265358979323846f) + 1.f) * 0.5f;

        float dl = pr0 - rd; dl *= dl;
        float g  = pr1 - ang;
        if (g < 0.f) g += 1.f;
        gaps[tid] = g;
        dls[tid]  = dl;
    }
    __syncthreads();

    // warp-shuffle mean of gaps
    if (tid < 32) {
        float t = (tid < HW) ? gaps[tid] : 0.f;
        if (tid + 32 < HW) t += gaps[tid + 32];
        #pragma unroll
        for (int off = 16; off > 0; off >>= 1)
            t += __shfl_down_sync(0xffffffffu, t, off);
        if (tid == 0) s_gmean = t * (1.f / (float)HW);
    }
    __syncthreads();

    if (tid < HW) {
        float g = gaps[tid] - s_gmean;
        out[n * HW + tid] = dls[tid] + g * g;
    }
}

extern "C" void kernel_launch(void* const* d_in, const int* in_sizes, int n_in,
                              void* d_out, int out_size)
{
    const float* x    = (const float*)d_in[0];
    const float* Wlin = (const float*)d_in[1];
    const float* b    = (const float*)d_in[2];
    float*       out  = (float*)d_out;

    const int N = in_sizes[0] / (CC * HW);   // 256

    float* scratch = nullptr;
    cudaGetSymbolAddress((void**)&scratch, g_scratch);

    rpcp_fused_kernel<<<N * SPLIT, NTHR>>>(x, Wlin, b, out, scratch);
}

// round 8
// speedup vs baseline: 1.1288x; 1.0077x over previous
#include <cuda_runtime.h>
#include <cuda_bf16.h>
#include <cuda_pipeline_primitives.h>
#include <cstdint>

#define CC      2048
#define HW      49
#define SIDE    7
#define CGROUPS 8
#define NTHR    512
#define SPLIT   8
#define CPS     (CC / SPLIT)          // 256 channels per CTA
#define NMAX    256
#define SLICE_FLOATS (CPS * HW)       // 12544 floats = 50176 B, contiguous
#define NCPY16  (SLICE_FLOATS / 4)    // 3136 x 16B copies

// scratch: [n][split][p][5]
__device__ float g_scratch[NMAX * SPLIT * HW * 5];
__device__ int   g_count[NMAX];       // zero-init; last block resets its slot

__global__ __launch_bounds__(NTHR, 2)
void rpcp_fused_kernel(const float* __restrict__ x,
                       const float* __restrict__ Wlin,
                       const float* __restrict__ bias,
                       float* __restrict__ out,
                       float* __restrict__ scratch)
{
    __shared__ alignas(128) float buf[SLICE_FLOATS];   // 50176 B
    __shared__ float4 wsh[CPS];                        // 4 KB
    __shared__ float  acc[CGROUPS][HW][5];
    __shared__ int    s_last;
    __shared__ float  fin[HW][5];
    __shared__ float  gaps[HW];
    __shared__ float  dls[HW];
    __shared__ int    s_idx;
    __shared__ float  s_gmean;

    const int tid = threadIdx.x;
    const int n   = blockIdx.x >> 3;            // SPLIT = 8
    const int sp  = blockIdx.x & (SPLIT - 1);
    const int c0  = sp * CPS;

    // bulk async copy of this CTA's contiguous 50 KB slice into smem.
    // 16B per cp.async, L1-bypass, ~3136 sectors in flight at once.
    {
        const float4* src = (const float4*)(x + (size_t)n * CC * HW + (size_t)c0 * HW);
        float4*       dst = (float4*)buf;
        for (int i = tid; i < NCPY16; i += NTHR)
            __pipeline_memcpy_async(dst + i, src + i, 16);
        __pipeline_commit();
    }

    // pack weight slice while copies fly: {W1_0, W1_1, W2_0, W2_1}
    for (int c = tid; c < CPS; c += NTHR) {
        const int cc = c0 + c;
        wsh[c] = make_float4(Wlin[cc],
                             Wlin[2 * CC + cc],
                             Wlin[CC + cc],
                             Wlin[3 * CC + cc]);
    }

    __pipeline_wait_prior(0);
    __syncthreads();

    const int p  = tid & 63;     // 0..48 active
    const int cg = tid >> 6;     // 0..7 (warp-uniform)

    if (p < HW) {
        float s = 0.f, a0 = 0.f, a1 = 0.f, d0 = 0.f, d1 = 0.f;
        #pragma unroll 8
        for (int u = 0; u < CPS / CGROUPS; u++) {    // 32 channels per thread
            const int c = cg + u * CGROUPS;
            const float  v = buf[c * HW + p];        // smem, conflict-light
            const float4 w = wsh[c];                 // warp-uniform broadcast
            s  += v;
            a0 = fmaf(v, w.x, a0);
            a1 = fmaf(v, w.y, a1);
            d0 = fmaf(v, w.z, d0);
            d1 = fmaf(v, w.w, d1);
        }
        acc[cg][p][0] = s;  acc[cg][p][1] = a0; acc[cg][p][2] = a1;
        acc[cg][p][3] = d0; acc[cg][p][4] = d1;
    }
    __syncthreads();

    if (tid < HW * 5) {
        const int pp = tid / 5, k = tid % 5;
        float t = 0.f;
        #pragma unroll
        for (int g = 0; g < CGROUPS; g++) t += acc[g][pp][k];
        scratch[((n * SPLIT + sp) * HW + pp) * 5 + k] = t;
    }

    // last-CTA-done handoff; fences by one thread only (cumulative via bar.sync)
    __syncthreads();
    if (tid == 0) {
        __threadfence();                       // release
        int old = atomicAdd(&g_count[n], 1);
        s_last = (old == SPLIT - 1);
        if (s_last) __threadfence();           // acquire
    }
    __syncthreads();
    if (!s_last) return;

    // ---- epilogue: this CTA finishes image n ----
    if (tid < HW * 5) {
        const int pp = tid / 5, k = tid % 5;
        float t = 0.f;
        #pragma unroll
        for (int g = 0; g < SPLIT; g++)
            t += scratch[((n * SPLIT + g) * HW + pp) * 5 + k];
        fin[pp][k] = t;
    }
    __syncthreads();

    // warp-shuffle argmax over channel-sum (first max wins ties)
    if (tid < 32) {
        float v  = fin[tid][0];
        int   bi = tid;
        if (tid + 32 < HW) {
            float v2 = fin[tid + 32][0];
            if (v2 > v) { v = v2; bi = tid + 32; }
        }
        #pragma unroll
        for (int off = 16; off > 0; off >>= 1) {
            float ov = __shfl_down_sync(0xffffffffu, v,  off);
            int   oi = __shfl_down_sync(0xffffffffu, bi, off);
            if (ov > v || (ov == v && oi < bi)) { v = ov; bi = oi; }
        }
        if (tid == 0) { s_idx = bi; g_count[n] = 0; }   // reset for replay
    }
    __syncthreads();
    const int idx = s_idx;

    if (tid < HW) {
        const float A0 = fin[idx][1];
        const float A1 = fin[idx][2];
        float pr0 = fin[tid][3] + A0 + bias[0];
        float pr1 = fin[tid][4] + A1 + bias[1];
        pr0 = fmaxf(pr0, 0.f);
        pr1 = fmaxf(pr1, 0.f);
        if (tid == idx) { pr0 = 0.f; pr1 = 0.f; }

        const float ri = (float)(tid / SIDE - idx / SIDE) * (1.f / (float)SIDE);
        const float rj = (float)(tid % SIDE - idx % SIDE) * (1.f / (float)SIDE);
        const float rd = sqrtf(ri * ri + rj * rj);
        const float ang = (atan2f(rj, ri) * (1.f / 3.14159265358979323846f) + 1.f) * 0.5f;

        float dl = pr0 - rd; dl *= dl;
        float g  = pr1 - ang;
        if (g < 0.f) g += 1.f;
        gaps[tid] = g;
        dls[tid]  = dl;
    }
    __syncthreads();

    // warp-shuffle mean of gaps
    if (tid < 32) {
        float t = (tid < HW) ? gaps[tid] : 0.f;
        if (tid + 32 < HW) t += gaps[tid + 32];
        #pragma unroll
        for (int off = 16; off > 0; off >>= 1)
            t += __shfl_down_sync(0xffffffffu, t, off);
        if (tid == 0) s_gmean = t * (1.f / (float)HW);
    }
    __syncthreads();

    if (tid < HW) {
        float g = gaps[tid] - s_gmean;
        out[n * HW + tid] = dls[tid] + g * g;
    }
}

extern "C" void kernel_launch(void* const* d_in, const int* in_sizes, int n_in,
                              void* d_out, int out_size)
{
    const float* x    = (const float*)d_in[0];
    const float* Wlin = (const float*)d_in[1];
    const float* b    = (const float*)d_in[2];
    float*       out  = (float*)d_out;

    const int N = in_sizes[0] / (CC * HW);   // 256

    float* scratch = nullptr;
    cudaGetSymbolAddress((void**)&scratch, g_scratch);

    rpcp_fused_kernel<<<N * SPLIT, NTHR>>>(x, Wlin, b, out, scratch);
}